// round 2
// baseline (speedup 1.0000x reference)
#include <cuda_runtime.h>
#include <cuda_bf16.h>

// ---------------- problem constants ----------------
#define EDG   16384
#define NNODE 512
#define NB    8
#define NT    16
#define HD    64            // C == H == 64
#define NSLAB (NB*NT)       // 128
#define NROW  (NB*NNODE)    // 4096 rows of state per step

// ---------------- device scratch (static; no allocation) ----------------
__device__ __align__(16) float g_deg[NNODE];
__device__ __align__(16) float g_dinv[NNODE];
__device__ int   g_cnt[NNODE];
__device__ int   g_rowptr[NNODE + 1];
__device__ int   g_cursor[NNODE];
__device__ __align__(16) int   g_col[EDG];
__device__ __align__(16) float g_val[EDG];
__device__ int   g_w64;     // 1 if edge_index buffer is int64, 0 if int32

__device__ __align__(16) float g_X1[NSLAB * NNODE * HD];   // Lx(x)  for all (b,t)
__device__ __align__(16) float g_X2[NSLAB * NNODE * HD];   // 2Lx(X1)-x

__device__ __align__(16) float g_h [NROW * HD];            // GRU state
__device__ __align__(16) float g_z [NROW * HD];
__device__ __align__(16) float g_hr[NROW * HD];
__device__ __align__(16) float g_U1[NROW * HD];            // reused as V1
__device__ __align__(16) float g_U2[NROW * HD];            // reused as V2

__device__ __align__(16) float g_Wzr[2][384 * 128];        // [l][kk][col] col=(g*64+h), g in {z,r}
__device__ __align__(16) float g_Wht[2][384 * 64];         // [l][kk][h]   (h-tilde gate)
__device__ __align__(16) float g_bzr[2][128];              // bx+bh per gate col
__device__ __align__(16) float g_bht[2][64];

__device__ __align__(16) float g_sp[NROW * HD];
__device__ __align__(16) float g_tp[NROW * HD];            // includes +b1

// ---------------- setup kernels ----------------
__global__ void k_init() {
    int i = blockIdx.x * blockDim.x + threadIdx.x;
    int nstate = NROW * HD;
    for (int j = i; j < nstate; j += gridDim.x * blockDim.x) g_h[j] = 0.f;
    if (i < NNODE) { g_deg[i] = 0.f; g_cnt[i] = 0; }
}

// Detect edge_index element width. If the buffer is int64 (little-endian),
// every odd 32-bit word is the high half of a value < 512 -> zero. If int32,
// odd words are random node ids; P(first 128 all zero) ~ 512^-128.
__global__ void k_detect(const int* __restrict__ ei32) {
    if (threadIdx.x == 0) {
        int any = 0;
        for (int i = 0; i < 128; ++i) any |= ei32[2 * i + 1];
        g_w64 = (any == 0) ? 1 : 0;
    }
}

__device__ __forceinline__ void load_edge(const void* ei, int e, int& s, int& d) {
    if (g_w64) {
        const long long* p = (const long long*)ei;
        s = (int)p[e]; d = (int)p[EDG + e];
    } else {
        const int* p = (const int*)ei;
        s = p[e]; d = p[EDG + e];
    }
}

__global__ void k_deg(const void* __restrict__ ei, const float* __restrict__ ew) {
    int e = blockIdx.x * blockDim.x + threadIdx.x;
    if (e >= EDG) return;
    int s, d;
    load_edge(ei, e, s, d);
    if ((unsigned)s >= NNODE || (unsigned)d >= NNODE) return;  // safety
    atomicAdd(&g_deg[s], ew[e]);
    atomicAdd(&g_cnt[d], 1);
}

__global__ void k_scan() {   // 1 block, 512 threads
    int i = threadIdx.x;
    float dg = g_deg[i];
    g_dinv[i] = (dg > 0.f) ? rsqrtf(fmaxf(dg, 1e-12f)) : 0.f;
    __shared__ int sc[NNODE];
    sc[i] = g_cnt[i];
    __syncthreads();
    for (int off = 1; off < NNODE; off <<= 1) {
        int v = (i >= off) ? sc[i - off] : 0;
        __syncthreads();
        sc[i] += v;
        __syncthreads();
    }
    if (i == 0) g_rowptr[0] = 0;
    g_rowptr[i + 1] = sc[i];
    g_cursor[i] = (i == 0) ? 0 : sc[i - 1];
}

__global__ void k_fill(const void* __restrict__ ei, const float* __restrict__ ew) {
    int e = blockIdx.x * blockDim.x + threadIdx.x;
    if (e >= EDG) return;
    int s, d;
    load_edge(ei, e, s, d);
    if ((unsigned)s >= NNODE || (unsigned)d >= NNODE) return;  // safety
    int p = atomicAdd(&g_cursor[d], 1);
    g_col[p] = s;
    g_val[p] = -ew[e] * g_dinv[s] * g_dinv[d];
}

// pack weights: rows kk = s*64+c with s<3 -> Wx[l,g,s], s>=3 -> Wh[l,g,s-3]
__global__ void k_wprep(const float* __restrict__ Wx, const float* __restrict__ bx,
                        const float* __restrict__ Wh, const float* __restrict__ bh) {
    int i = blockIdx.x * blockDim.x + threadIdx.x;
    if (i < 98304) {                      // Wzr: 2 * 384 * 128
        int l = i / 49152, rem = i % 49152;
        int kk = rem / 128, col = rem % 128;
        int s = kk >> 6, c = kk & 63, g = col >> 6, h = col & 63;
        float v = (s < 3) ? Wx[((((l*3+g)*3 + s)*64) + c)*64 + h]
                          : Wh[((((l*3+g)*3 + (s-3))*64) + c)*64 + h];
        g_Wzr[l][kk*128 + col] = v;
    } else if (i < 98304 + 49152) {       // Wht: 2 * 384 * 64
        int j = i - 98304;
        int l = j / 24576, rem = j % 24576;
        int kk = rem / 64, h = rem % 64;
        int s = kk >> 6, c = kk & 63;
        float v = (s < 3) ? Wx[((((l*3+2)*3 + s)*64) + c)*64 + h]
                          : Wh[((((l*3+2)*3 + (s-3))*64) + c)*64 + h];
        g_Wht[l][kk*64 + h] = v;
    } else if (i < 147456 + 256) {        // bzr
        int j = i - 147456;
        int l = j / 128, col = j % 128;
        int g = col >> 6, h = col & 63;
        g_bzr[l][col] = bx[(l*3+g)*64 + h] + bh[(l*3+g)*64 + h];
    } else if (i < 147712 + 128) {        // bht
        int j = i - 147712;
        int l = j / 64, h = j % 64;
        g_bht[l][h] = bx[(l*3+2)*64 + h] + bh[(l*3+2)*64 + h];
    }
}

// ---------------- SpMM: out[slab,n,:] = alpha * sum_e val*u[slab,col,:]  (- sub) ----------------
__global__ void __launch_bounds__(256) k_spmm(const float* __restrict__ u,
                                              const float* __restrict__ sub,
                                              float alpha,
                                              float* __restrict__ out) {
    int slab = blockIdx.y;
    int node = blockIdx.x * 8 + (threadIdx.x >> 5);
    int lane = threadIdx.x & 31;
    long base = (long)slab * NNODE * HD;
    int rs = g_rowptr[node], re = g_rowptr[node + 1];
    float a0 = 0.f, a1 = 0.f;
    for (int e = rs; e < re; ++e) {
        int s = g_col[e];
        float v = g_val[e];
        const float* up = u + base + s * HD;
        a0 += v * up[lane];
        a1 += v * up[lane + 32];
    }
    float o0 = alpha * a0, o1 = alpha * a1;
    long ob = base + (long)node * HD;
    if (sub) { o0 -= sub[ob + lane]; o1 -= sub[ob + lane + 32]; }
    out[ob + lane]      = o0;
    out[ob + lane + 32] = o1;
}

// ---------------- fused step GEMM ----------------
// A = [x_t | X1_t | X2_t | d0 | d1 | d2]  (K = 384), B row-major [384][NTOT]
// MODE 1: NTOT=128, epilogue sigmoid -> z, hr = r*h
// MODE 2: NTOT=64,  epilogue tanh   -> h = z*h + (1-z)*htilde
template<int BM, int BN, int MODE>
__global__ void __launch_bounds__(256) k_gemm(
    const float* __restrict__ xa, const float* __restrict__ xb, const float* __restrict__ xc,
    const float* __restrict__ da, const float* __restrict__ db, const float* __restrict__ dc,
    const float* __restrict__ Bmat, const float* __restrict__ bias, int t) {
    constexpr int NTOT = (MODE == 1) ? 128 : 64;
    constexpr int TM = BM / 16, TN = BN / 16;
    __shared__ float As[16][BM];
    __shared__ float Bs[16][BN];
    int tid = threadIdx.x;
    int tx = tid & 15, ty = tid >> 4;
    int row0 = blockIdx.x * BM;
    int n0 = blockIdx.y * BN;
    float acc[TM][TN];
#pragma unroll
    for (int i = 0; i < TM; ++i)
#pragma unroll
        for (int j = 0; j < TN; ++j) acc[i][j] = 0.f;

    for (int kt = 0; kt < 24; ++kt) {
        int s = kt >> 2;
        int koff = (kt & 3) * 16;
        const float* asrc = (s == 0) ? xa : (s == 1) ? xb : (s == 2) ? xc
                          : (s == 3) ? da : (s == 4) ? db : dc;
        bool xl = (s < 3);
        // load A tile (transposed into As[k][m])
        for (int q = tid; q < BM * 4; q += 256) {
            int m = q >> 2, kq = q & 3;
            int gr = row0 + m;
            int sr = xl ? ((((gr >> 9) * NT + t) << 9) | (gr & 511)) : gr;
            float4 v = *reinterpret_cast<const float4*>(asrc + (long)sr * HD + koff + kq * 4);
            As[kq*4 + 0][m] = v.x; As[kq*4 + 1][m] = v.y;
            As[kq*4 + 2][m] = v.z; As[kq*4 + 3][m] = v.w;
        }
        // load B tile
        constexpr int QPK = BN / 4;
        for (int q = tid; q < BN * 4; q += 256) {
            int kk = q / QPK, nq = q % QPK;
            float4 v = *reinterpret_cast<const float4*>(Bmat + (long)(kt*16 + kk) * NTOT + n0 + nq * 4);
            *reinterpret_cast<float4*>(&Bs[kk][nq * 4]) = v;
        }
        __syncthreads();
#pragma unroll
        for (int k = 0; k < 16; ++k) {
            float a[TM], b[TN];
#pragma unroll
            for (int i = 0; i < TM; ++i) a[i] = As[k][ty * TM + i];
#pragma unroll
            for (int j = 0; j < TN; ++j) b[j] = Bs[k][tx * TN + j];
#pragma unroll
            for (int i = 0; i < TM; ++i)
#pragma unroll
                for (int j = 0; j < TN; ++j) acc[i][j] += a[i] * b[j];
        }
        __syncthreads();
    }

#pragma unroll
    for (int i = 0; i < TM; ++i) {
        int row = row0 + ty * TM + i;
#pragma unroll
        for (int j = 0; j < TN; ++j) {
            int col = n0 + tx * TN + j;
            float pre = acc[i][j] + bias[col];
            if (MODE == 1) {
                float sg = 1.f / (1.f + __expf(-pre));
                int g = col >> 6, hc = col & 63;
                if (g == 0) g_z[row * HD + hc] = sg;
                else        g_hr[row * HD + hc] = sg * g_h[row * HD + hc];
            } else {
                float th = tanhf(pre);
                float z  = g_z[row * HD + col];
                float ho = g_h[row * HD + col];
                g_h[row * HD + col] = z * ho + (1.f - z) * th;
            }
        }
    }
}

// ---------------- link predictor ----------------
__global__ void k_proj(const float* __restrict__ W1, const float* __restrict__ b1) {
    int r = blockIdx.x;             // 0..4095
    int j = threadIdx.x;            // 0..127
    __shared__ float hrow[HD];
    if (j < HD) hrow[j] = g_h[(long)r * HD + j];
    __syncthreads();
    int hc = j & 63;
    bool isT = (j >= 64);
    int off = isT ? 64 : 0;
    float acc = 0.f;
#pragma unroll 8
    for (int c = 0; c < HD; ++c) acc += hrow[c] * W1[(off + c) * 64 + hc];
    if (isT) g_tp[(long)r * HD + hc] = acc + b1[hc];
    else     g_sp[(long)r * HD + hc] = acc;
}

__global__ void __launch_bounds__(256) k_pair(const float* __restrict__ W2,
                                              const float* __restrict__ b2,
                                              float* __restrict__ out) {
    __shared__ float ssp[32][65];
    __shared__ float stp[32][65];
    __shared__ float sw2[64];
    int b  = blockIdx.z;
    int s0 = blockIdx.y * 32;
    int t0 = blockIdx.x * 32;
    int tid = threadIdx.x;
    for (int q = tid; q < 32 * 64; q += 256) {
        int row = q >> 6, c = q & 63;
        ssp[row][c] = g_sp[((long)(b * NNODE + s0 + row)) * HD + c];
        stp[row][c] = g_tp[((long)(b * NNODE + t0 + row)) * HD + c];
    }
    if (tid < 64) sw2[tid] = W2[tid];
    __syncthreads();
    int si = tid >> 3;
    int tb = (tid & 7) * 4;
    float a0 = 0.f, a1 = 0.f, a2 = 0.f, a3 = 0.f;
#pragma unroll 4
    for (int h = 0; h < HD; ++h) {
        float a = ssp[si][h];
        float w = sw2[h];
        a0 += fmaxf(a + stp[tb + 0][h], 0.f) * w;
        a1 += fmaxf(a + stp[tb + 1][h], 0.f) * w;
        a2 += fmaxf(a + stp[tb + 2][h], 0.f) * w;
        a3 += fmaxf(a + stp[tb + 3][h], 0.f) * w;
    }
    float bb = b2[0];
    long ob = ((long)(b * NNODE + s0 + si)) * NNODE + t0 + tb;
    out[ob + 0] = a0 + bb;
    out[ob + 1] = a1 + bb;
    out[ob + 2] = a2 + bb;
    out[ob + 3] = a3 + bb;
}

// ---------------- launch ----------------
extern "C" void kernel_launch(void* const* d_in, const int* in_sizes, int n_in,
                              void* d_out, int out_size) {
    const float* x  = (const float*)d_in[0];
    const float* ew = (const float*)d_in[1];
    const float* Wx = (const float*)d_in[2];
    const float* bx = (const float*)d_in[3];
    const float* Wh = (const float*)d_in[4];
    const float* bh = (const float*)d_in[5];
    const float* W1 = (const float*)d_in[6];
    const float* b1 = (const float*)d_in[7];
    const float* W2 = (const float*)d_in[8];
    const float* b2 = (const float*)d_in[9];
    const void*  ei = d_in[10];                 // int32 or int64 -> detected on device
    float* out = (float*)d_out;

    float *pX1, *pX2, *ph, *phr, *pU1, *pU2, *pWzr, *pWht, *pbzr, *pbht;
    cudaGetSymbolAddress((void**)&pX1,  g_X1);
    cudaGetSymbolAddress((void**)&pX2,  g_X2);
    cudaGetSymbolAddress((void**)&ph,   g_h);
    cudaGetSymbolAddress((void**)&phr,  g_hr);
    cudaGetSymbolAddress((void**)&pU1,  g_U1);
    cudaGetSymbolAddress((void**)&pU2,  g_U2);
    cudaGetSymbolAddress((void**)&pWzr, g_Wzr);
    cudaGetSymbolAddress((void**)&pWht, g_Wht);
    cudaGetSymbolAddress((void**)&pbzr, g_bzr);
    cudaGetSymbolAddress((void**)&pbht, g_bht);

    // graph structure + weight packing
    k_init<<<256, 1024>>>();
    k_detect<<<1, 32>>>((const int*)ei);
    k_deg<<<(EDG + 255) / 256, 256>>>(ei, ew);
    k_scan<<<1, NNODE>>>();
    k_fill<<<(EDG + 255) / 256, 256>>>(ei, ew);
    k_wprep<<<(147840 + 255) / 256, 256>>>(Wx, bx, Wh, bh);

    // x Chebyshev basis for all (b,t) slabs
    k_spmm<<<dim3(NNODE / 8, NSLAB), 256>>>(x,    nullptr, 1.f, pX1);
    k_spmm<<<dim3(NNODE / 8, NSLAB), 256>>>(pX1,  x,       2.f, pX2);

    // recurrent steps
    for (int t = 0; t < NT; ++t) {
        for (int l = 0; l < 2; ++l) {
            // h basis
            k_spmm<<<dim3(NNODE / 8, NB), 256>>>(ph,  nullptr, 1.f, pU1);
            k_spmm<<<dim3(NNODE / 8, NB), 256>>>(pU1, ph,      2.f, pU2);
            // z, r gates (+ hr)
            k_gemm<64, 64, 1><<<dim3(NROW / 64, 2), 256>>>(
                x, pX1, pX2, ph, pU1, pU2,
                pWzr + (long)l * 384 * 128, pbzr + (long)l * 128, t);
            // hr basis (reuse U1/U2)
            k_spmm<<<dim3(NNODE / 8, NB), 256>>>(phr, nullptr, 1.f, pU1);
            k_spmm<<<dim3(NNODE / 8, NB), 256>>>(pU1, phr,     2.f, pU2);
            // h-tilde + state update
            k_gemm<32, 64, 2><<<dim3(NROW / 32, 1), 256>>>(
                x, pX1, pX2, phr, pU1, pU2,
                pWht + (long)l * 384 * 64, pbht + (long)l * 64, t);
        }
    }

    // predictor
    k_proj<<<NROW, 128>>>(W1, b1);
    k_pair<<<dim3(NNODE / 32, NNODE / 32, NB), 256>>>(W2, b2, out);
}